// round 2
// baseline (speedup 1.0000x reference)
#include <cuda_runtime.h>
#include <math.h>

// Problem constants
#define Bc 2
#define Sc 2048
#define Dc 1024
#define Hc 16
#define DKc 64
#define Mtot (Bc * Sc)          // 4096
#define KT_STRIDE 68            // padded k-major K tile stride (floats)

// Scratch (device globals — no runtime allocation allowed)
__device__ float gQ[Bc * Hc * Sc * DKc];   // [b,h,s,dk]
__device__ float gK[Bc * Hc * Sc * DKc];
__device__ float gV[Bc * Hc * Sc * DKc];
__device__ float gA[Mtot * Dc];            // attn output, [b,s,h*dk]

// ---------------------------------------------------------------------------
// Tiled SGEMM: C[m][n] = sum_k A[m][k] * W[n][k] + bias[n]
// (torch Linear convention: y = x @ W.T + b; W is [N,K] row-major)
// Block tile 128x128, K-step 8, 256 threads, 8x8 microtile per thread.
// ---------------------------------------------------------------------------
template <bool HEAD_LAYOUT>
__device__ __forceinline__ void gemm_body(const float* __restrict__ A,
                                          const float* __restrict__ W,
                                          const float* __restrict__ bias,
                                          float* __restrict__ C) {
    __shared__ float As[8 * 132];
    __shared__ float Bs[8 * 132];

    const int tid = threadIdx.x;
    const int tx = tid & 15;
    const int ty = tid >> 4;
    const int m0 = blockIdx.y * 128;
    const int n0 = blockIdx.x * 128;

    const int lrow = tid >> 1;          // 0..127
    const int lk4 = (tid & 1) * 4;      // 0 or 4

    const float* Ap = A + (size_t)(m0 + lrow) * Dc + lk4;
    const float* Wp = W + (size_t)(n0 + lrow) * Dc + lk4;

    float acc[8][8];
#pragma unroll
    for (int i = 0; i < 8; i++)
#pragma unroll
        for (int j = 0; j < 8; j++) acc[i][j] = 0.f;

    // software-pipelined gmem load
    float4 av = *(const float4*)(Ap);
    float4 wv = *(const float4*)(Wp);

    for (int k0 = 0; k0 < Dc; k0 += 8) {
        __syncthreads();
        As[(lk4 + 0) * 132 + lrow] = av.x;
        As[(lk4 + 1) * 132 + lrow] = av.y;
        As[(lk4 + 2) * 132 + lrow] = av.z;
        As[(lk4 + 3) * 132 + lrow] = av.w;
        Bs[(lk4 + 0) * 132 + lrow] = wv.x;
        Bs[(lk4 + 1) * 132 + lrow] = wv.y;
        Bs[(lk4 + 2) * 132 + lrow] = wv.z;
        Bs[(lk4 + 3) * 132 + lrow] = wv.w;
        __syncthreads();

        if (k0 + 8 < Dc) {
            av = *(const float4*)(Ap + k0 + 8);
            wv = *(const float4*)(Wp + k0 + 8);
        }

#pragma unroll
        for (int kk = 0; kk < 8; kk++) {
            float4 a0 = *(const float4*)&As[kk * 132 + 4 * ty];
            float4 a1 = *(const float4*)&As[kk * 132 + 64 + 4 * ty];
            float4 b0 = *(const float4*)&Bs[kk * 132 + 4 * tx];
            float4 b1 = *(const float4*)&Bs[kk * 132 + 64 + 4 * tx];
            float a[8] = {a0.x, a0.y, a0.z, a0.w, a1.x, a1.y, a1.z, a1.w};
            float b[8] = {b0.x, b0.y, b0.z, b0.w, b1.x, b1.y, b1.z, b1.w};
#pragma unroll
            for (int i = 0; i < 8; i++)
#pragma unroll
                for (int j = 0; j < 8; j++)
                    acc[i][j] = fmaf(a[i], b[j], acc[i][j]);
        }
    }

#pragma unroll
    for (int i = 0; i < 8; i++) {
        const int mi = m0 + ((i < 4) ? (4 * ty + i) : (64 + 4 * ty + i - 4));
#pragma unroll
        for (int j = 0; j < 8; j++) {
            const int nj = n0 + ((j < 4) ? (4 * tx + j) : (64 + 4 * tx + j - 4));
            const float v = acc[i][j] + bias[nj];
            if (HEAD_LAYOUT) {
                // out[b, h, s, dk]
                const int bb = mi / Sc;
                const int s = mi - bb * Sc;
                const int h = nj >> 6;
                const int dk = nj & 63;
                C[(((size_t)(bb * Hc + h)) * Sc + s) * DKc + dk] = v;
            } else {
                C[(size_t)mi * Dc + nj] = v;
            }
        }
    }
}

__global__ __launch_bounds__(256) void qkv_kernel(
    const float* __restrict__ X,
    const float* __restrict__ Wq, const float* __restrict__ bq,
    const float* __restrict__ Wk, const float* __restrict__ bk,
    const float* __restrict__ Wv, const float* __restrict__ bv) {
    const float* W = Wq;
    const float* bias = bq;
    float* out = gQ;
    if (blockIdx.z == 1) { W = Wk; bias = bk; out = gK; }
    else if (blockIdx.z == 2) { W = Wv; bias = bv; out = gV; }
    gemm_body<true>(X, W, bias, out);
}

__global__ __launch_bounds__(256) void oproj_kernel(
    const float* __restrict__ Wo, const float* __restrict__ bo,
    float* __restrict__ out) {
    gemm_body<false>(gA, Wo, bo, out);
}

// ---------------------------------------------------------------------------
// Flash attention: one block per (64-row q tile, b*h). 256 threads (16x16),
// each thread owns a 4x4 score microtile and 4x4 output columns.
// ---------------------------------------------------------------------------
__global__ __launch_bounds__(256) void flash_kernel(const int* __restrict__ mask) {
    extern __shared__ float sm[];
    float* Qs = sm;                      // [64][64]   row-major (pre-scaled)
    float* Kt = Qs + 64 * 64;            // [64][68]   k-major (transposed)
    float* Vs = Kt + 64 * KT_STRIDE;     // [64][64]   row-major
    float* Ps = Vs + 64 * 64;            // [64][64]   row-major

    const int tid = threadIdx.x;
    const int tx = tid & 15;
    const int ty = tid >> 4;
    const int q0 = blockIdx.x * 64;
    const int bh = blockIdx.y;

    const float* Qg = gQ + (size_t)(bh * Sc + q0) * DKc;
    const float* Kg = gK + (size_t)bh * Sc * DKc;
    const float* Vg = gV + (size_t)bh * Sc * DKc;

    // Load Q tile, pre-scaled by 1/sqrt(dk) = 0.125
#pragma unroll
    for (int it = 0; it < 4; it++) {
        const int idx = tid + it * 256;
        const int r = idx >> 4;
        const int c4 = (idx & 15) << 2;
        float4 v = *(const float4*)(Qg + (size_t)r * DKc + c4);
        v.x *= 0.125f; v.y *= 0.125f; v.z *= 0.125f; v.w *= 0.125f;
        *(float4*)(Qs + r * 64 + c4) = v;
    }

    float m_i[4], l_i[4], o[4][4];
#pragma unroll
    for (int i = 0; i < 4; i++) {
        m_i[i] = -INFINITY;
        l_i[i] = 0.f;
#pragma unroll
        for (int j = 0; j < 4; j++) o[i][j] = 0.f;
    }

    for (int kt = 0; kt < Sc / 64; kt++) {
        const int k0 = kt * 64;
        __syncthreads();  // protect Kt/Vs/Ps from previous iteration readers
#pragma unroll
        for (int it = 0; it < 4; it++) {
            const int idx = tid + it * 256;
            const int r = idx >> 4;
            const int c4 = (idx & 15) << 2;
            float4 kv = *(const float4*)(Kg + (size_t)(k0 + r) * DKc + c4);
            Kt[(c4 + 0) * KT_STRIDE + r] = kv.x;
            Kt[(c4 + 1) * KT_STRIDE + r] = kv.y;
            Kt[(c4 + 2) * KT_STRIDE + r] = kv.z;
            Kt[(c4 + 3) * KT_STRIDE + r] = kv.w;
            float4 vv = *(const float4*)(Vg + (size_t)(k0 + r) * DKc + c4);
            *(float4*)(Vs + r * 64 + c4) = vv;
        }
        __syncthreads();

        // scores: s[i][j] = sum_k Qs[4ty+i][k] * Kt[k][4tx+j]  (already scaled)
        float s[4][4];
#pragma unroll
        for (int i = 0; i < 4; i++)
#pragma unroll
            for (int j = 0; j < 4; j++) s[i][j] = 0.f;

#pragma unroll 8
        for (int k = 0; k < 64; k++) {
            float q[4];
#pragma unroll
            for (int i = 0; i < 4; i++) q[i] = Qs[(4 * ty + i) * 64 + k];
            const float4 kb = *(const float4*)&Kt[k * KT_STRIDE + 4 * tx];
            const float b4[4] = {kb.x, kb.y, kb.z, kb.w};
#pragma unroll
            for (int i = 0; i < 4; i++)
#pragma unroll
                for (int j = 0; j < 4; j++)
                    s[i][j] = fmaf(q[i], b4[j], s[i][j]);
        }

        // mask (shape [1,1,S,S]); nonzero = keep
#pragma unroll
        for (int i = 0; i < 4; i++) {
            const int4 mk = *(const int4*)(mask + (size_t)(q0 + 4 * ty + i) * Sc + k0 + 4 * tx);
            if (mk.x == 0) s[i][0] = -1e9f;
            if (mk.y == 0) s[i][1] = -1e9f;
            if (mk.z == 0) s[i][2] = -1e9f;
            if (mk.w == 0) s[i][3] = -1e9f;
        }

        // online softmax (row groups = 16 consecutive lanes)
#pragma unroll
        for (int i = 0; i < 4; i++) {
            float mx = fmaxf(fmaxf(s[i][0], s[i][1]), fmaxf(s[i][2], s[i][3]));
#pragma unroll
            for (int off = 8; off >= 1; off >>= 1)
                mx = fmaxf(mx, __shfl_xor_sync(0xffffffffu, mx, off, 16));
            const float mnew = fmaxf(m_i[i], mx);
            const float corr = __expf(m_i[i] - mnew);
            m_i[i] = mnew;
            float rs = 0.f;
#pragma unroll
            for (int j = 0; j < 4; j++) {
                s[i][j] = __expf(s[i][j] - mnew);
                rs += s[i][j];
            }
#pragma unroll
            for (int off = 8; off >= 1; off >>= 1)
                rs += __shfl_xor_sync(0xffffffffu, rs, off, 16);
            l_i[i] = l_i[i] * corr + rs;
#pragma unroll
            for (int j = 0; j < 4; j++) o[i][j] *= corr;
        }

        // stage P in smem (conflict-free float4 writes, broadcast reads)
#pragma unroll
        for (int i = 0; i < 4; i++)
            *(float4*)&Ps[(4 * ty + i) * 64 + 4 * tx] =
                make_float4(s[i][0], s[i][1], s[i][2], s[i][3]);
        __syncthreads();

        // O += P @ V
#pragma unroll 8
        for (int k = 0; k < 64; k++) {
            float p[4];
#pragma unroll
            for (int i = 0; i < 4; i++) p[i] = Ps[(4 * ty + i) * 64 + k];
            const float4 vb = *(const float4*)&Vs[k * 64 + 4 * tx];
            const float v4[4] = {vb.x, vb.y, vb.z, vb.w};
#pragma unroll
            for (int i = 0; i < 4; i++)
#pragma unroll
                for (int j = 0; j < 4; j++)
                    o[i][j] = fmaf(p[i], v4[j], o[i][j]);
        }
    }

    // write normalized output to gA in [b, s, h*dk] layout
    const int b = bh >> 4;
    const int h = bh & 15;
#pragma unroll
    for (int i = 0; i < 4; i++) {
        const float inv = 1.f / l_i[i];
        const int row = q0 + 4 * ty + i;
        float* dst = gA + (size_t)(b * Sc + row) * Dc + h * DKc + 4 * tx;
        *(float4*)dst = make_float4(o[i][0] * inv, o[i][1] * inv,
                                    o[i][2] * inv, o[i][3] * inv);
    }
}

// ---------------------------------------------------------------------------
extern "C" void kernel_launch(void* const* d_in, const int* in_sizes, int n_in,
                              void* d_out, int out_size) {
    const float* X  = (const float*)d_in[0];
    const int* mask = (const int*)d_in[1];
    const float* Wq = (const float*)d_in[2];
    const float* bq = (const float*)d_in[3];
    const float* Wk = (const float*)d_in[4];
    const float* bk = (const float*)d_in[5];
    const float* Wv = (const float*)d_in[6];
    const float* bv = (const float*)d_in[7];
    const float* Wo = (const float*)d_in[8];
    const float* bo = (const float*)d_in[9];
    float* out = (float*)d_out;

    const int flash_smem = (64 * 64 * 3 + 64 * KT_STRIDE) * (int)sizeof(float); // 66560 B
    cudaFuncSetAttribute(flash_kernel,
                         cudaFuncAttributeMaxDynamicSharedMemorySize, flash_smem);

    dim3 gq(Dc / 128, Mtot / 128, 3);
    qkv_kernel<<<gq, 256>>>(X, Wq, bq, Wk, bk, Wv, bv);

    dim3 gf(Sc / 64, Bc * Hc);
    flash_kernel<<<gf, 256, flash_smem>>>(mask);

    dim3 go(Dc / 128, Mtot / 128);
    oproj_kernel<<<go, 256>>>(Wo, bo, out);
}

// round 3
// speedup vs baseline: 2.3789x; 2.3789x over previous
#include <cuda_runtime.h>
#include <math.h>
#include <stdint.h>

#define Sc 2048
#define Dc 1024
#define Hc 16
#define DKc 64
#define Mtot 4096

#define LOG2E_SCALE 0.18033688011112042f   // 0.125 * log2(e)
#define MASKVAL     (-1.4426950408889634e9f) // -1e9 * log2(e)

// Scratch
__device__ float gQ[2 * Hc * Sc * DKc];   // [b,h,s,dk]
__device__ float gK[2 * Hc * Sc * DKc];
__device__ float gV[2 * Hc * Sc * DKc];
__device__ float gA[Mtot * Dc];           // attn out, [b,s,h*dk]
__device__ int gMaskFlag[16 * 32];        // [qtile128][ktile64] all-ones flags

#define SW(k) ((((k) & 3) ^ (((k) >> 2) & 3)) << 3)

__device__ __forceinline__ uint32_t f2tf(float f) {
    uint32_t u;
    asm("cvt.rna.tf32.f32 %0, %1;" : "=r"(u) : "f"(f));
    return u;
}
__device__ __forceinline__ float fexp2(float x) {
    float r;
    asm("ex2.approx.f32 %0, %1;" : "=f"(r) : "f"(x));
    return r;
}
__device__ __forceinline__ void mma8(float* c, const uint32_t* a, uint32_t b0, uint32_t b1) {
    asm volatile(
        "mma.sync.aligned.m16n8k8.row.col.f32.tf32.tf32.f32 "
        "{%0,%1,%2,%3},{%4,%5,%6,%7},{%8,%9},{%0,%1,%2,%3};\n"
        : "+f"(c[0]), "+f"(c[1]), "+f"(c[2]), "+f"(c[3])
        : "r"(a[0]), "r"(a[1]), "r"(a[2]), "r"(a[3]), "r"(b0), "r"(b1));
}

// ---------------------------------------------------------------------------
// tf32 GEMM: C[m][n] = sum_k A[m][k]*W[n][k] + bias[n]
// 128x128 tile, BK=16, 256 threads, 8 warps (2m x 4n), warp tile 64x32.
// ---------------------------------------------------------------------------
template <bool HEAD>
__device__ __forceinline__ void gemm_tf32(const float* __restrict__ A,
                                          const float* __restrict__ W,
                                          const float* __restrict__ bias,
                                          float* __restrict__ C) {
    __shared__ uint32_t As[16 * 128];
    __shared__ uint32_t Bs[16 * 128];

    const int tid = threadIdx.x, lane = tid & 31, warp = tid >> 5;
    const int wm = warp >> 2, wn = warp & 3;
    const int e = lane >> 2, la = lane & 3;
    const int m0 = blockIdx.y * 128, n0 = blockIdx.x * 128;
    const int r = tid >> 2, q = tid & 3;

    const float* Ap = A + (size_t)(m0 + r) * Dc + 4 * q;
    const float* Wp = W + (size_t)(n0 + r) * Dc + 4 * q;

    float acc[4][4][4];
#pragma unroll
    for (int mi = 0; mi < 4; mi++)
#pragma unroll
        for (int ni = 0; ni < 4; ni++)
#pragma unroll
            for (int t = 0; t < 4; t++) acc[mi][ni][t] = 0.f;

    float4 pa0 = *(const float4*)(Ap);
    float4 pa1 = *(const float4*)(Ap + 64 * Dc);
    float4 pw0 = *(const float4*)(Wp);
    float4 pw1 = *(const float4*)(Wp + 64 * Dc);

    for (int k0 = 0; k0 < Dc; k0 += 16) {
        __syncthreads();
        {
            const float va0[4] = {pa0.x, pa0.y, pa0.z, pa0.w};
            const float va1[4] = {pa1.x, pa1.y, pa1.z, pa1.w};
            const float vw0[4] = {pw0.x, pw0.y, pw0.z, pw0.w};
            const float vw1[4] = {pw1.x, pw1.y, pw1.z, pw1.w};
#pragma unroll
            for (int j = 0; j < 4; j++) {
                const int k = 4 * q + j;
                const int sw = SW(k);
                As[k * 128 + (r ^ sw)] = f2tf(va0[j]);
                As[k * 128 + ((r + 64) ^ sw)] = f2tf(va1[j]);
                Bs[k * 128 + (r ^ sw)] = f2tf(vw0[j]);
                Bs[k * 128 + ((r + 64) ^ sw)] = f2tf(vw1[j]);
            }
        }
        __syncthreads();

        if (k0 + 16 < Dc) {
            pa0 = *(const float4*)(Ap + k0 + 16);
            pa1 = *(const float4*)(Ap + 64 * Dc + k0 + 16);
            pw0 = *(const float4*)(Wp + k0 + 16);
            pw1 = *(const float4*)(Wp + 64 * Dc + k0 + 16);
        }

#pragma unroll
        for (int ks = 0; ks < 2; ks++) {
            const int kb = 8 * ks;
            uint32_t af[4][4], bf[4][2];
#pragma unroll
            for (int mi = 0; mi < 4; mi++) {
                const int mr = 64 * wm + 16 * mi;
                af[mi][0] = As[(kb + la) * 128 + ((mr + e) ^ SW(kb + la))];
                af[mi][1] = As[(kb + la) * 128 + ((mr + e + 8) ^ SW(kb + la))];
                af[mi][2] = As[(kb + la + 4) * 128 + ((mr + e) ^ SW(kb + la + 4))];
                af[mi][3] = As[(kb + la + 4) * 128 + ((mr + e + 8) ^ SW(kb + la + 4))];
            }
#pragma unroll
            for (int ni = 0; ni < 4; ni++) {
                const int nc = 32 * wn + 8 * ni;
                bf[ni][0] = Bs[(kb + la) * 128 + ((nc + e) ^ SW(kb + la))];
                bf[ni][1] = Bs[(kb + la + 4) * 128 + ((nc + e) ^ SW(kb + la + 4))];
            }
#pragma unroll
            for (int mi = 0; mi < 4; mi++)
#pragma unroll
                for (int ni = 0; ni < 4; ni++)
                    mma8(acc[mi][ni], af[mi], bf[ni][0], bf[ni][1]);
        }
    }

#pragma unroll
    for (int mi = 0; mi < 4; mi++) {
#pragma unroll
        for (int ni = 0; ni < 4; ni++) {
            const int nc = n0 + 32 * wn + 8 * ni + 2 * la;
            const float b0 = bias[nc], b1 = bias[nc + 1];
#pragma unroll
            for (int half = 0; half < 2; half++) {
                const int mr = m0 + 64 * wm + 16 * mi + e + 8 * half;
                const float v0 = acc[mi][ni][2 * half] + b0;
                const float v1 = acc[mi][ni][2 * half + 1] + b1;
                if (HEAD) {
                    const int bb = mr >> 11;
                    const int s = mr & 2047;
                    const int h = nc >> 6, dk = nc & 63;
                    *(float2*)(C + (((size_t)(bb * Hc + h)) * Sc + s) * DKc + dk) =
                        make_float2(v0, v1);
                } else {
                    *(float2*)(C + (size_t)mr * Dc + nc) = make_float2(v0, v1);
                }
            }
        }
    }
}

__global__ __launch_bounds__(256, 2) void qkv_kernel(
    const float* __restrict__ X,
    const float* __restrict__ Wq, const float* __restrict__ bq,
    const float* __restrict__ Wk, const float* __restrict__ bk,
    const float* __restrict__ Wv, const float* __restrict__ bv) {
    const float* W = Wq;
    const float* bias = bq;
    float* out = gQ;
    if (blockIdx.z == 1) { W = Wk; bias = bk; out = gK; }
    else if (blockIdx.z == 2) { W = Wv; bias = bv; out = gV; }
    gemm_tf32<true>(X, W, bias, out);
}

__global__ __launch_bounds__(256, 2) void oproj_kernel(
    const float* __restrict__ Wo, const float* __restrict__ bo,
    float* __restrict__ out) {
    gemm_tf32<false>(gA, Wo, bo, out);
}

// ---------------------------------------------------------------------------
// Mask tile flags: flag = 1 iff the 128x64 mask tile is all nonzero.
// ---------------------------------------------------------------------------
__global__ __launch_bounds__(256) void mask_flags_kernel(const int* __restrict__ mask) {
    const int qt = blockIdx.x >> 5, kt = blockIdx.x & 31;
    const int tid = threadIdx.x;
    int ok = 1;
#pragma unroll
    for (int i = 0; i < 8; i++) {
        const int idx = tid + 256 * i;          // 0..2047
        const int row = idx >> 4, c4 = (idx & 15) * 4;
        const int4 v = *(const int4*)(mask + (size_t)(qt * 128 + row) * Sc + kt * 64 + c4);
        ok &= (v.x != 0) & (v.y != 0) & (v.z != 0) & (v.w != 0);
    }
    ok = __syncthreads_and(ok);
    if (tid == 0) gMaskFlag[blockIdx.x] = ok;
}

// ---------------------------------------------------------------------------
// Flash attention, tf32 MMA. Block: 256 thr (8 warps), q-tile 128, kv-tile 64.
// Warp w owns q rows 16w..16w+15. Q a-frags live in registers.
// smem: Qs [dk64][q128] swizzled | KsPs: Ks [dk64][kv64] swz / Ps [q128][68] | Vs [kv64][72]
// ---------------------------------------------------------------------------
__global__ __launch_bounds__(256, 1) void flash_kernel(const int* __restrict__ mask) {
    extern __shared__ uint32_t smu[];
    uint32_t* Qs = smu;                 // 8192 u32
    uint32_t* KsPs = smu + 8192;        // max(4096, 8704) = 8704 u32
    uint32_t* Vs = smu + 8192 + 8704;   // 4608 u32

    const int tid = threadIdx.x, lane = tid & 31, warp = tid >> 5;
    const int e = lane >> 2, la = lane & 3;
    const int qt = blockIdx.x, bh = blockIdx.y;
    const int q0 = qt * 128;

    const float* Qg = gQ + (size_t)bh * Sc * DKc + (size_t)q0 * DKc;
    const float* Kg = gK + (size_t)bh * Sc * DKc;
    const float* Vg = gV + (size_t)bh * Sc * DKc;

    // Load + transpose Q -> Qs (scaled, tf32)
    {
        const int r = tid >> 2, qd = tid & 3;
#pragma unroll
        for (int half = 0; half < 2; half++) {
            const int row = r + 64 * half;
#pragma unroll
            for (int i = 0; i < 4; i++) {
                const int kq = qd + 4 * i;
                float4 v = *(const float4*)(Qg + (size_t)row * DKc + 4 * kq);
                const float vv[4] = {v.x, v.y, v.z, v.w};
#pragma unroll
                for (int j = 0; j < 4; j++) {
                    const int dk = 4 * kq + j;
                    Qs[dk * 128 + (row ^ SW(dk))] = f2tf(vv[j] * LOG2E_SCALE);
                }
            }
        }
    }
    __syncthreads();

    // Q a-frags in registers
    uint32_t qa[8][4];
    {
        const int mr = 16 * warp;
#pragma unroll
        for (int ks = 0; ks < 8; ks++) {
            const int kb = 8 * ks;
            qa[ks][0] = Qs[(kb + la) * 128 + ((mr + e) ^ SW(kb + la))];
            qa[ks][1] = Qs[(kb + la) * 128 + ((mr + e + 8) ^ SW(kb + la))];
            qa[ks][2] = Qs[(kb + la + 4) * 128 + ((mr + e) ^ SW(kb + la + 4))];
            qa[ks][3] = Qs[(kb + la + 4) * 128 + ((mr + e + 8) ^ SW(kb + la + 4))];
        }
    }

    float o[8][4];
#pragma unroll
    for (int nb = 0; nb < 8; nb++)
#pragma unroll
        for (int t = 0; t < 4; t++) o[nb][t] = 0.f;
    float m0r = -1e30f, m1r = -1e30f, l0r = 0.f, l1r = 0.f;

    const int* flagp = gMaskFlag + qt * 32;

    for (int kt = 0; kt < 32; kt++) {
        const int k0 = kt * 64;
        __syncthreads();  // prev tile's PV reads of Ps/Vs complete

        // K tile -> Ks [dk][kv] transposed swizzled tf32
        {
            const int r = tid >> 2, qd = tid & 3;   // r = kv row
#pragma unroll
            for (int i = 0; i < 4; i++) {
                const int kq = qd + 4 * i;
                float4 v = *(const float4*)(Kg + (size_t)(k0 + r) * DKc + 4 * kq);
                const float vv[4] = {v.x, v.y, v.z, v.w};
#pragma unroll
                for (int j = 0; j < 4; j++) {
                    const int dk = 4 * kq + j;
                    KsPs[dk * 64 + (r ^ SW(dk))] = f2tf(vv[j]);
                }
            }
            // V tile -> Vs [kv][dk] stride 72, tf32
            const int rv = tid >> 4, c4 = (tid & 15) * 4;
#pragma unroll
            for (int i = 0; i < 4; i++) {
                const int row = rv + 16 * i;
                float4 v = *(const float4*)(Vg + (size_t)(k0 + row) * DKc + c4);
                Vs[row * 72 + c4 + 0] = f2tf(v.x);
                Vs[row * 72 + c4 + 1] = f2tf(v.y);
                Vs[row * 72 + c4 + 2] = f2tf(v.z);
                Vs[row * 72 + c4 + 3] = f2tf(v.w);
            }
        }
        __syncthreads();

        // S = Q K^T (log2 domain)
        float s[8][4];
#pragma unroll
        for (int nb = 0; nb < 8; nb++)
#pragma unroll
            for (int t = 0; t < 4; t++) s[nb][t] = 0.f;
#pragma unroll
        for (int ks = 0; ks < 8; ks++) {
            const int kb = 8 * ks;
#pragma unroll
            for (int nb = 0; nb < 8; nb++) {
                const int n = 8 * nb;
                const uint32_t b0 = KsPs[(kb + la) * 64 + ((n + e) ^ SW(kb + la))];
                const uint32_t b1 = KsPs[(kb + la + 4) * 64 + ((n + e) ^ SW(kb + la + 4))];
                mma8(s[nb], qa[ks], b0, b1);
            }
        }

        // mask (fast path: tile all ones)
        if (!flagp[kt]) {
#pragma unroll
            for (int nb = 0; nb < 8; nb++) {
                const int col = k0 + 8 * nb + 2 * la;
                const int* mp0 = mask + (size_t)(q0 + 16 * warp + e) * Sc + col;
                const int* mp1 = mask + (size_t)(q0 + 16 * warp + e + 8) * Sc + col;
                if (mp0[0] == 0) s[nb][0] = MASKVAL;
                if (mp0[1] == 0) s[nb][1] = MASKVAL;
                if (mp1[0] == 0) s[nb][2] = MASKVAL;
                if (mp1[1] == 0) s[nb][3] = MASKVAL;
            }
        }

        // online softmax (base-2)
        float mx0 = -1e30f, mx1 = -1e30f;
#pragma unroll
        for (int nb = 0; nb < 8; nb++) {
            mx0 = fmaxf(mx0, fmaxf(s[nb][0], s[nb][1]));
            mx1 = fmaxf(mx1, fmaxf(s[nb][2], s[nb][3]));
        }
        mx0 = fmaxf(mx0, __shfl_xor_sync(0xffffffffu, mx0, 1));
        mx0 = fmaxf(mx0, __shfl_xor_sync(0xffffffffu, mx0, 2));
        mx1 = fmaxf(mx1, __shfl_xor_sync(0xffffffffu, mx1, 1));
        mx1 = fmaxf(mx1, __shfl_xor_sync(0xffffffffu, mx1, 2));
        const float mn0 = fmaxf(m0r, mx0), mn1 = fmaxf(m1r, mx1);
        const float c0 = fexp2(m0r - mn0), c1 = fexp2(m1r - mn1);
        m0r = mn0; m1r = mn1;
        float sum0 = 0.f, sum1 = 0.f;
#pragma unroll
        for (int nb = 0; nb < 8; nb++) {
            s[nb][0] = fexp2(s[nb][0] - mn0); sum0 += s[nb][0];
            s[nb][1] = fexp2(s[nb][1] - mn0); sum0 += s[nb][1];
            s[nb][2] = fexp2(s[nb][2] - mn1); sum1 += s[nb][2];
            s[nb][3] = fexp2(s[nb][3] - mn1); sum1 += s[nb][3];
        }
        sum0 += __shfl_xor_sync(0xffffffffu, sum0, 1);
        sum0 += __shfl_xor_sync(0xffffffffu, sum0, 2);
        sum1 += __shfl_xor_sync(0xffffffffu, sum1, 1);
        sum1 += __shfl_xor_sync(0xffffffffu, sum1, 2);
        l0r = l0r * c0 + sum0;
        l1r = l1r * c1 + sum1;
#pragma unroll
        for (int nb = 0; nb < 8; nb++) {
            o[nb][0] *= c0; o[nb][1] *= c0; o[nb][2] *= c1; o[nb][3] *= c1;
        }

        __syncthreads();  // all warps finished reading Ks -> reuse region as Ps

        // write P (tf32) to Ps [128][68]
        {
            const int r0 = 16 * warp + e, r1 = r0 + 8;
#pragma unroll
            for (int nb = 0; nb < 8; nb++) {
                const int col = 8 * nb + 2 * la;
                KsPs[r0 * 68 + col + 0] = f2tf(s[nb][0]);
                KsPs[r0 * 68 + col + 1] = f2tf(s[nb][1]);
                KsPs[r1 * 68 + col + 0] = f2tf(s[nb][2]);
                KsPs[r1 * 68 + col + 1] = f2tf(s[nb][3]);
            }
        }
        __syncwarp();

        // O += P @ V
#pragma unroll
        for (int ks = 0; ks < 8; ks++) {
            const int kb = 8 * ks;
            uint32_t pa[4];
            const int row = 16 * warp;
            pa[0] = KsPs[(row + e) * 68 + kb + la];
            pa[1] = KsPs[(row + e + 8) * 68 + kb + la];
            pa[2] = KsPs[(row + e) * 68 + kb + la + 4];
            pa[3] = KsPs[(row + e + 8) * 68 + kb + la + 4];
#pragma unroll
            for (int nb = 0; nb < 8; nb++) {
                const uint32_t b0 = Vs[(kb + la) * 72 + 8 * nb + e];
                const uint32_t b1 = Vs[(kb + la + 4) * 72 + 8 * nb + e];
                mma8(o[nb], pa, b0, b1);
            }
        }
    }

    // epilogue -> gA [b, s, h*64 + dk]
    const float inv0 = 1.f / l0r, inv1 = 1.f / l1r;
    const int b = bh >> 4, h = bh & 15;
    const int r0 = q0 + 16 * warp + e, r1 = r0 + 8;
#pragma unroll
    for (int nb = 0; nb < 8; nb++) {
        const int col = h * 64 + 8 * nb + 2 * la;
        *(float2*)(gA + (size_t)(b * Sc + r0) * Dc + col) =
            make_float2(o[nb][0] * inv0, o[nb][1] * inv0);
        *(float2*)(gA + (size_t)(b * Sc + r1) * Dc + col) =
            make_float2(o[nb][2] * inv1, o[nb][3] * inv1);
    }
}

// ---------------------------------------------------------------------------
extern "C" void kernel_launch(void* const* d_in, const int* in_sizes, int n_in,
                              void* d_out, int out_size) {
    const float* X  = (const float*)d_in[0];
    const int* mask = (const int*)d_in[1];
    const float* Wq = (const float*)d_in[2];
    const float* bq = (const float*)d_in[3];
    const float* Wk = (const float*)d_in[4];
    const float* bk = (const float*)d_in[5];
    const float* Wv = (const float*)d_in[6];
    const float* bv = (const float*)d_in[7];
    const float* Wo = (const float*)d_in[8];
    const float* bo = (const float*)d_in[9];
    float* out = (float*)d_out;

    const int flash_smem = (8192 + 8704 + 4608) * 4;  // 86016 B
    static int attr_set = 0;
    if (!attr_set) {
        cudaFuncSetAttribute(flash_kernel,
                             cudaFuncAttributeMaxDynamicSharedMemorySize, flash_smem);
        attr_set = 1;
    }

    mask_flags_kernel<<<512, 256>>>(mask);

    dim3 gq(Dc / 128, Mtot / 128, 3);
    qkv_kernel<<<gq, 256>>>(X, Wq, bq, Wk, bk, Wv, bv);

    dim3 gf(Sc / 128, 2 * Hc);
    flash_kernel<<<gf, 256, flash_smem>>>(mask);

    dim3 go(Dc / 128, Mtot / 128);
    oproj_kernel<<<go, 256>>>(Wo, bo, out);
}